// round 11
// baseline (speedup 1.0000x reference)
#include <cuda_runtime.h>
#include <cuda_bf16.h>
#include <cuda_fp16.h>
#include <math.h>
#include <stdint.h>

// Problem shape (fixed by the dataset)
#define NG 16384   // n_genes
#define NL 4096    // n_latent (softmax axis, GEMM-K)
#define DK 64      // d_k
#define NC 1024    // n_cells
#define OUT_ELEMS (NG * NC)
#define PSCALE 1024.0f
#define INV_PSCALE (1.0f / 1024.0f)

__device__ __half g_Ph[(size_t)NG * NL];    // 134 MB  fp16(P*1024)
__device__ __half g_VhT[(size_t)NC * NL];   // 8 MB    V^T fp16  [n][k]

__device__ __forceinline__ uint32_t smem_to_u32(const void* p) {
    uint32_t a;
    asm("{ .reg .u64 t; cvta.to.shared.u64 t, %1; cvt.u32.u64 %0, t; }" : "=r"(a) : "l"(p));
    return a;
}
__device__ __forceinline__ void ldsm4(uint32_t* r, uint32_t addr) {
    asm volatile("ldmatrix.sync.aligned.m8n8.x4.shared.b16 {%0,%1,%2,%3}, [%4];"
                 : "=r"(r[0]), "=r"(r[1]), "=r"(r[2]), "=r"(r[3]) : "r"(addr));
}
__device__ __forceinline__ void mma_f16(float* c, const uint32_t* a,
                                        uint32_t b0, uint32_t b1) {
    asm volatile("mma.sync.aligned.m16n8k16.row.col.f32.f16.f16.f32 "
                 "{%0,%1,%2,%3}, {%4,%5,%6,%7}, {%8,%9}, {%0,%1,%2,%3};"
                 : "+f"(c[0]), "+f"(c[1]), "+f"(c[2]), "+f"(c[3])
                 : "r"(a[0]), "r"(a[1]), "r"(a[2]), "r"(a[3]), "r"(b0), "r"(b1));
}
__device__ __forceinline__ void cpa16(uint32_t dst, const void* src) {
    asm volatile("cp.async.cg.shared.global [%0], [%1], 16;" :: "r"(dst), "l"(src));
}
#define CP_COMMIT() asm volatile("cp.async.commit_group;" ::: "memory")
#define CP_WAIT1()  asm volatile("cp.async.wait_group 1;" ::: "memory")

// ---------------------------------------------------------------------------
// JAX threefry2x32 Gumbel noise, partitionable mode, key (0, 42)
// ---------------------------------------------------------------------------
__device__ __forceinline__ float gumbel_at(uint32_t e) {
    uint32_t x0 = 0u, x1 = e;
    const uint32_t ks1 = 42u;
    const uint32_t ks2 = 0x1BD11BDAu ^ 42u;
    x1 += ks1;
#define TFR(r) { x0 += x1; x1 = __funnelshift_l(x1, x1, (r)); x1 ^= x0; }
    TFR(13) TFR(15) TFR(26) TFR(6)
    x0 += ks1; x1 += ks2 + 1u;
    TFR(17) TFR(29) TFR(16) TFR(24)
    x0 += ks2; x1 += 2u;
    TFR(13) TFR(15) TFR(26) TFR(6)
    x1 += ks1 + 3u;
    TFR(17) TFR(29) TFR(16) TFR(24)
    x0 += ks1; x1 += ks2 + 4u;
    TFR(13) TFR(15) TFR(26) TFR(6)
    x0 += ks2; x1 += 5u;
#undef TFR
    uint32_t bits = x0 ^ x1;
    float f = __uint_as_float(0x3F800000u | (bits >> 9)) - 1.0f;
    float t = 1.0f - f;   // exact
    float poly = 1.0f / 7.0f;
    poly = fmaf(poly, t, 1.0f / 6.0f);
    poly = fmaf(poly, t, 0.2f);
    poly = fmaf(poly, t, 0.25f);
    poly = fmaf(poly, t, 1.0f / 3.0f);
    poly = fmaf(poly, t, 0.5f);
    poly = fmaf(poly, t, 1.0f);
    float w_ser = t * poly;
    float w_muf = -__logf(f);
    float w = (t < 0.105f) ? w_ser : w_muf;
    w = (f > 0.0f) ? w : 87.33654475f;
    return -__logf(w);
}

// ---------------------------------------------------------------------------
// Kernel A: S = (Q @ K^T)/8 + gumbel — fp16 hi/lo 3-product tensor GEMM.
// CTA 128x128 tile, 8 warps (2x4), warp 64x32, K=64 in one smem phase.
// ---------------------------------------------------------------------------
#define SSP 72                         // smem stride fp16 (144 B rows)
#define SC_ARR (128 * SSP * 2)         // 18432 B per array
#define SC_SMEM (4 * SC_ARR)           // 73728 B (Qhi,Qlo,Khi,Klo)

__global__ __launch_bounds__(256, 2)
void score_kernel(const float* __restrict__ Q, const float* __restrict__ Km,
                  float* __restrict__ S)
{
    extern __shared__ __align__(16) char ssm[];
    const uint32_t sb = smem_to_u32(ssm);
    const uint32_t uQh = sb, uQl = sb + SC_ARR, uKh = sb + 2 * SC_ARR, uKl = sb + 3 * SC_ARR;

    const int tid = threadIdx.x;
    const int lane = tid & 31, wid = tid >> 5;
    const int wm = wid >> 2, wn = wid & 3;
    const int bn = blockIdx.x, bm = blockIdx.y;

    // load + split Q,K tiles (each 128 rows x 64 fp32)
#pragma unroll
    for (int u = 0; u < 8; u++) {
        int idx = tid + 256 * u;        // 0..2047: 128 rows x 16 c4
        int row = idx >> 4, c4 = idx & 15;
        float4 vq = *(const float4*)(Q + (size_t)(bm * 128 + row) * DK + c4 * 4);
        float4 vk = *(const float4*)(Km + (size_t)(bn * 128 + row) * DK + c4 * 4);
        uint32_t off = (row * SSP + c4 * 4) * 2;
        __half hx, hy, hz, hw;
        hx = __float2half_rn(vq.x); hy = __float2half_rn(vq.y);
        hz = __float2half_rn(vq.z); hw = __float2half_rn(vq.w);
        __half2 qh01 = __halves2half2(hx, hy), qh23 = __halves2half2(hz, hw);
        __half2 ql01 = __halves2half2(__float2half_rn(vq.x - __half2float(hx)),
                                      __float2half_rn(vq.y - __half2float(hy)));
        __half2 ql23 = __halves2half2(__float2half_rn(vq.z - __half2float(hz)),
                                      __float2half_rn(vq.w - __half2float(hw)));
        *(uint2*)(ssm + (uQh - sb) + off) = make_uint2(*(uint32_t*)&qh01, *(uint32_t*)&qh23);
        *(uint2*)(ssm + (uQl - sb) + off) = make_uint2(*(uint32_t*)&ql01, *(uint32_t*)&ql23);
        hx = __float2half_rn(vk.x); hy = __float2half_rn(vk.y);
        hz = __float2half_rn(vk.z); hw = __float2half_rn(vk.w);
        __half2 kh01 = __halves2half2(hx, hy), kh23 = __halves2half2(hz, hw);
        __half2 kl01 = __halves2half2(__float2half_rn(vk.x - __half2float(hx)),
                                      __float2half_rn(vk.y - __half2float(hy)));
        __half2 kl23 = __halves2half2(__float2half_rn(vk.z - __half2float(hz)),
                                      __float2half_rn(vk.w - __half2float(hw)));
        *(uint2*)(ssm + (uKh - sb) + off) = make_uint2(*(uint32_t*)&kh01, *(uint32_t*)&kh23);
        *(uint2*)(ssm + (uKl - sb) + off) = make_uint2(*(uint32_t*)&kl01, *(uint32_t*)&kl23);
    }
    __syncthreads();

    float acc[4][4][4];
#pragma unroll
    for (int i = 0; i < 4; i++)
#pragma unroll
        for (int j = 0; j < 4; j++)
#pragma unroll
            for (int q = 0; q < 4; q++) acc[i][j][q] = 0.0f;

    const int lrow = (lane & 7) + ((lane >> 3) & 1) * 8;
    const int lcol8 = (lane >> 4) * 8;

#pragma unroll
    for (int kk = 0; kk < 64; kk += 16) {
        const uint32_t boff = ((wn * 32 + lrow) * SSP + kk + lcol8) * 2;
        uint32_t bh[2][4], bl[2][4];
#pragma unroll
        for (int np = 0; np < 2; np++) {
            ldsm4(bh[np], uKh + boff + np * (16 * SSP * 2));
            ldsm4(bl[np], uKl + boff + np * (16 * SSP * 2));
        }
        const uint32_t aoff = ((wm * 64 + lrow) * SSP + kk + lcol8) * 2;
#pragma unroll
        for (int mt = 0; mt < 4; mt++) {
            uint32_t ah[4], al[4];
            ldsm4(ah, uQh + aoff + mt * (16 * SSP * 2));
            ldsm4(al, uQl + aoff + mt * (16 * SSP * 2));
#pragma unroll
            for (int nt = 0; nt < 4; nt++) {
                const int np = nt >> 1, sel = nt & 1;
                mma_f16(acc[mt][nt], ah, bh[np][sel], bh[np][sel + 2]);
                mma_f16(acc[mt][nt], ah, bl[np][sel], bl[np][sel + 2]);
                mma_f16(acc[mt][nt], al, bh[np][sel], bh[np][sel + 2]);
            }
        }
    }

    // Epilogue: scale 1/8, add gumbel, store fp32 scores
#pragma unroll
    for (int mt = 0; mt < 4; mt++) {
        uint32_t m0 = bm * 128 + wm * 64 + mt * 16 + (lane >> 2);
#pragma unroll
        for (int nt = 0; nt < 4; nt++) {
            uint32_t col = bn * 128 + wn * 32 + nt * 8 + 2 * (lane & 3);
            uint32_t e0 = m0 * (uint32_t)NL + col;
            uint32_t e1 = (m0 + 8) * (uint32_t)NL + col;
            float2 v0, v1;
            v0.x = acc[mt][nt][0] * 0.125f + gumbel_at(e0);
            v0.y = acc[mt][nt][1] * 0.125f + gumbel_at(e0 + 1);
            v1.x = acc[mt][nt][2] * 0.125f + gumbel_at(e1);
            v1.y = acc[mt][nt][3] * 0.125f + gumbel_at(e1 + 1);
            *(float2*)(S + e0) = v0;
            *(float2*)(S + e1) = v1;
        }
    }
}

// ---------------------------------------------------------------------------
// Kernel B: in-place row softmax + fused fp16 conversion of P (scaled x1024)
// ---------------------------------------------------------------------------
__global__ __launch_bounds__(256)
void softmax_kernel(float* __restrict__ P)
{
    __shared__ float4 row4[NL / 4];
    __shared__ float red[8];
    const int r = blockIdx.x, t = threadIdx.x;
    float4* g = (float4*)(P + (size_t)r * NL);

    float mx = -INFINITY;
#pragma unroll
    for (int q = 0; q < 4; q++) {
        float4 v = g[t + 256 * q];
        row4[t + 256 * q] = v;
        mx = fmaxf(mx, fmaxf(fmaxf(v.x, v.y), fmaxf(v.z, v.w)));
    }
#pragma unroll
    for (int o = 16; o > 0; o >>= 1)
        mx = fmaxf(mx, __shfl_xor_sync(0xffffffffu, mx, o));
    if ((t & 31) == 0) red[t >> 5] = mx;
    __syncthreads();
    mx = red[0];
#pragma unroll
    for (int w = 1; w < 8; w++) mx = fmaxf(mx, red[w]);
    __syncthreads();

    float s = 0.0f;
#pragma unroll
    for (int q = 0; q < 4; q++) {
        float4 v = row4[t + 256 * q];
        v.x = __expf(v.x - mx); v.y = __expf(v.y - mx);
        v.z = __expf(v.z - mx); v.w = __expf(v.w - mx);
        row4[t + 256 * q] = v;
        s += (v.x + v.y) + (v.z + v.w);
    }
#pragma unroll
    for (int o = 16; o > 0; o >>= 1)
        s += __shfl_xor_sync(0xffffffffu, s, o);
    if ((t & 31) == 0) red[t >> 5] = s;
    __syncthreads();
    float tot = red[0];
#pragma unroll
    for (int w = 1; w < 8; w++) tot += red[w];
    float inv = 1.0f / tot;
    __syncthreads();

    uint2* ph = (uint2*)(g_Ph + (size_t)r * NL);
#pragma unroll
    for (int q = 0; q < 4; q++) {
        float4 v = row4[t + 256 * q];
        v.x *= inv; v.y *= inv; v.z *= inv; v.w *= inv;
        g[t + 256 * q] = v;
        __half2 h01 = __floats2half2_rn(v.x * PSCALE, v.y * PSCALE);
        __half2 h23 = __floats2half2_rn(v.z * PSCALE, v.w * PSCALE);
        ph[t + 256 * q] = make_uint2(*(uint32_t*)&h01, *(uint32_t*)&h23);
    }
}

// ---------------------------------------------------------------------------
// Kernel B2: transpose V to fp16:  V[k][n] -> V^T fp16 [n][k]
// ---------------------------------------------------------------------------
__global__ __launch_bounds__(256)
void vsplit_kernel(const float* __restrict__ V)
{
    __shared__ float tile[32][33];
    const int n0 = blockIdx.x * 32, k0 = blockIdx.y * 32;
    const int tx = threadIdx.x & 31, ty = threadIdx.x >> 5;
#pragma unroll
    for (int i = 0; i < 32; i += 8)
        tile[ty + i][tx] = V[(size_t)(k0 + ty + i) * NC + n0 + tx];
    __syncthreads();
#pragma unroll
    for (int i = 0; i < 32; i += 8) {
        float f = tile[tx][ty + i];
        g_VhT[(size_t)(n0 + ty + i) * NL + k0 + tx] = __float2half_rn(f);
    }
}

// ---------------------------------------------------------------------------
// Kernel C: out = P @ V, fp16 mma.sync (Ph*Vh), fp32 accum.
// CTA tile 64x256, 128 threads (4 warps across n), WARP TILE 64x64:
// 8 LDSM feed 32 MMAs per kk-batch (vs 6:16 before). BK=32, 3 stages.
// ---------------------------------------------------------------------------
#define SP 40
#define P_ARR (64 * SP * 2)            // 5120 B
#define V_ARR (256 * SP * 2)           // 20480 B
#define STAGE_BYTES (P_ARR + V_ARR)    // 25600 B
#define NSTAGE 3
#define PV_SMEM (NSTAGE * STAGE_BYTES) // 76800 B

__global__ __launch_bounds__(128, 2)
void pv_kernel(float* __restrict__ O)
{
    extern __shared__ __align__(16) char dsm[];
    const uint32_t sbase = smem_to_u32(dsm);

    const int tid = threadIdx.x;
    const int lane = tid & 31, wn = tid >> 5;        // 4 warps across n
    const int bn = blockIdx.x, bm = blockIdx.y;      // bn: 4, bm: 256

    const __half* srcP = g_Ph  + (size_t)(bm * 64) * NL;
    const __half* srcV = g_VhT + (size_t)(bn * 256) * NL;

    float acc[4][8][4];
#pragma unroll
    for (int i = 0; i < 4; i++)
#pragma unroll
        for (int j = 0; j < 8; j++)
#pragma unroll
            for (int q = 0; q < 4; q++) acc[i][j][q] = 0.0f;

    const int lrow = (lane & 7) + ((lane >> 3) & 1) * 8;
    const int lcol8 = (lane >> 4) * 8;

    auto load_stage = [&](int st, int k0) {
        uint32_t stb = sbase + st * STAGE_BYTES;
        // P: 64 rows x 4 kc = 256 slots, 2 per thread
#pragma unroll
        for (int u = 0; u < 2; u++) {
            int idx = tid + 128 * u;
            int row = idx >> 2, kc = idx & 3;
            cpa16(stb + (row * SP + kc * 8) * 2, srcP + (size_t)row * NL + k0 + kc * 8);
        }
        // V: 256 rows x 4 kc = 1024 slots, 8 per thread
#pragma unroll
        for (int u = 0; u < 8; u++) {
            int idx = tid + 128 * u;
            int row = idx >> 2, kc = idx & 3;
            cpa16(stb + P_ARR + (row * SP + kc * 8) * 2, srcV + (size_t)row * NL + k0 + kc * 8);
        }
    };

    load_stage(0, 0);  CP_COMMIT();
    load_stage(1, 32); CP_COMMIT();

    const int NCH = NL / 32;   // 128 chunks
    for (int c = 0; c < NCH; c++) {
        CP_WAIT1();
        __syncthreads();
        if (c + 2 < NCH) load_stage((c + 2) % NSTAGE, (c + 2) * 32);
        CP_COMMIT();

        const uint32_t stb = sbase + (c % NSTAGE) * STAGE_BYTES;
        const uint32_t uPh = stb, uVh = stb + P_ARR;

#pragma unroll
        for (int kk = 0; kk < 32; kk += 16) {
            const uint32_t aoff = (lrow * SP + kk + lcol8) * 2;
            const uint32_t boff = ((wn * 64 + lrow) * SP + kk + lcol8) * 2;
            uint32_t ah[4][4];
#pragma unroll
            for (int mt = 0; mt < 4; mt++)
                ldsm4(ah[mt], uPh + aoff + mt * (16 * SP * 2));
            uint32_t bh[4][4];
#pragma unroll
            for (int np = 0; np < 4; np++)
                ldsm4(bh[np], uVh + boff + np * (16 * SP * 2));
#pragma unroll
            for (int mt = 0; mt < 4; mt++)
#pragma unroll
                for (int nt = 0; nt < 8; nt++) {
                    const int np = nt >> 1, sel = nt & 1;
                    mma_f16(acc[mt][nt], ah[mt], bh[np][sel], bh[np][sel + 2]);
                }
        }
    }

    // Epilogue (undo the 1024x P scaling)
#pragma unroll
    for (int mt = 0; mt < 4; mt++) {
        int m = bm * 64 + mt * 16 + (lane >> 2);
#pragma unroll
        for (int nt = 0; nt < 8; nt++) {
            int col = bn * 256 + wn * 64 + nt * 8 + 2 * (lane & 3);
            float2 v0 = make_float2(acc[mt][nt][0] * INV_PSCALE,
                                    acc[mt][nt][1] * INV_PSCALE);
            float2 v1 = make_float2(acc[mt][nt][2] * INV_PSCALE,
                                    acc[mt][nt][3] * INV_PSCALE);
            *(float2*)(O + (size_t)m * NC + col)       = v0;
            *(float2*)(O + (size_t)(m + 8) * NC + col) = v1;
        }
    }
}

// ---------------------------------------------------------------------------
// Launch
// ---------------------------------------------------------------------------
extern "C" void kernel_launch(void* const* d_in, const int* in_sizes, int n_in,
                              void* d_out, int out_size) {
    const float* Q  = (const float*)d_in[0];   // [16384, 64]
    const float* Km = (const float*)d_in[1];   // [4096, 64]
    const float* V  = (const float*)d_in[2];   // [4096, 1024]
    float* out = (float*)d_out;                // [16384, 1024]
    float* P   = out + OUT_ELEMS;              // [16384, 4096] p_attn

    static bool attr_done = false;
    if (!attr_done) {
        cudaFuncSetAttribute(pv_kernel, cudaFuncAttributeMaxDynamicSharedMemorySize,
                             PV_SMEM);
        cudaFuncSetAttribute(score_kernel, cudaFuncAttributeMaxDynamicSharedMemorySize,
                             SC_SMEM);
        attr_done = true;
    }

    dim3 gA(NL / 128, NG / 128);               // 32 x 128
    score_kernel<<<gA, 256, SC_SMEM>>>(Q, Km, P);

    vsplit_kernel<<<dim3(NC / 32, NL / 32), 256>>>(V);

    softmax_kernel<<<NG, 256>>>(P);

    dim3 gC(NC / 256, NG / 64);                // 4 x 256
    pv_kernel<<<gC, 128, PV_SMEM>>>(out);
}

// round 13
// speedup vs baseline: 1.0866x; 1.0866x over previous
#include <cuda_runtime.h>
#include <cuda_bf16.h>
#include <cuda_fp16.h>
#include <math.h>
#include <stdint.h>

#define NG 16384
#define NL 4096
#define DK 64
#define NC 1024
#define OUT_ELEMS (NG * NC)
#define ESHIFT 13.0f

// Eh = fp16(exp(s - 13)) lives here (unnormalized softmax numerators)
__device__ __half g_Eh[(size_t)NG * NL];    // 134 MB
__device__ __half g_VhT[(size_t)NC * NL];   // 8 MB   V^T fp16 [n][k]
__device__ float  g_inv[NG];                // per-row 1/sum

__device__ __forceinline__ uint32_t smem_to_u32(const void* p) {
    uint32_t a;
    asm("{ .reg .u64 t; cvta.to.shared.u64 t, %1; cvt.u32.u64 %0, t; }" : "=r"(a) : "l"(p));
    return a;
}
__device__ __forceinline__ void ldsm4(uint32_t* r, uint32_t addr) {
    asm volatile("ldmatrix.sync.aligned.m8n8.x4.shared.b16 {%0,%1,%2,%3}, [%4];"
                 : "=r"(r[0]), "=r"(r[1]), "=r"(r[2]), "=r"(r[3]) : "r"(addr));
}
__device__ __forceinline__ void mma_f16(float* c, const uint32_t* a,
                                        uint32_t b0, uint32_t b1) {
    asm volatile("mma.sync.aligned.m16n8k16.row.col.f32.f16.f16.f32 "
                 "{%0,%1,%2,%3}, {%4,%5,%6,%7}, {%8,%9}, {%0,%1,%2,%3};"
                 : "+f"(c[0]), "+f"(c[1]), "+f"(c[2]), "+f"(c[3])
                 : "r"(a[0]), "r"(a[1]), "r"(a[2]), "r"(a[3]), "r"(b0), "r"(b1));
}
__device__ __forceinline__ void cpa16(uint32_t dst, const void* src) {
    asm volatile("cp.async.cg.shared.global [%0], [%1], 16;" :: "r"(dst), "l"(src));
}
#define CP_COMMIT() asm volatile("cp.async.commit_group;" ::: "memory")
#define CP_WAIT1()  asm volatile("cp.async.wait_group 1;" ::: "memory")

// ---------------------------------------------------------------------------
// JAX threefry2x32 Gumbel noise, partitionable mode, key (0, 42)
// ---------------------------------------------------------------------------
__device__ __forceinline__ float gumbel_at(uint32_t e) {
    uint32_t x0 = 0u, x1 = e;
    const uint32_t ks1 = 42u;
    const uint32_t ks2 = 0x1BD11BDAu ^ 42u;
    x1 += ks1;
#define TFR(r) { x0 += x1; x1 = __funnelshift_l(x1, x1, (r)); x1 ^= x0; }
    TFR(13) TFR(15) TFR(26) TFR(6)
    x0 += ks1; x1 += ks2 + 1u;
    TFR(17) TFR(29) TFR(16) TFR(24)
    x0 += ks2; x1 += 2u;
    TFR(13) TFR(15) TFR(26) TFR(6)
    x1 += ks1 + 3u;
    TFR(17) TFR(29) TFR(16) TFR(24)
    x0 += ks1; x1 += ks2 + 4u;
    TFR(13) TFR(15) TFR(26) TFR(6)
    x0 += ks2; x1 += 5u;
#undef TFR
    uint32_t bits = x0 ^ x1;
    float f = __uint_as_float(0x3F800000u | (bits >> 9)) - 1.0f;
    float t = 1.0f - f;   // exact
    float poly = 1.0f / 7.0f;
    poly = fmaf(poly, t, 1.0f / 6.0f);
    poly = fmaf(poly, t, 0.2f);
    poly = fmaf(poly, t, 0.25f);
    poly = fmaf(poly, t, 1.0f / 3.0f);
    poly = fmaf(poly, t, 0.5f);
    poly = fmaf(poly, t, 1.0f);
    float w_ser = t * poly;
    float w_muf = -__logf(f);
    float w = (t < 0.105f) ? w_ser : w_muf;
    w = (f > 0.0f) ? w : 87.33654475f;
    return -__logf(w);
}

// ---------------------------------------------------------------------------
// Kernel A: Eh = fp16(exp((QK^T/8 + gumbel) - 13)) — fp16 hi/lo 3-product GEMM
// ---------------------------------------------------------------------------
#define SSP 72
#define SC_ARR (128 * SSP * 2)
#define SC_SMEM (4 * SC_ARR)

__global__ __launch_bounds__(256, 2)
void score_kernel(const float* __restrict__ Q, const float* __restrict__ Km)
{
    extern __shared__ __align__(16) char ssm[];
    const uint32_t sb = smem_to_u32(ssm);
    const uint32_t uQh = sb, uQl = sb + SC_ARR, uKh = sb + 2 * SC_ARR, uKl = sb + 3 * SC_ARR;

    const int tid = threadIdx.x;
    const int lane = tid & 31, wid = tid >> 5;
    const int wm = wid >> 2, wn = wid & 3;
    const int bn = blockIdx.x, bm = blockIdx.y;

#pragma unroll
    for (int u = 0; u < 8; u++) {
        int idx = tid + 256 * u;
        int row = idx >> 4, c4 = idx & 15;
        float4 vq = *(const float4*)(Q + (size_t)(bm * 128 + row) * DK + c4 * 4);
        float4 vk = *(const float4*)(Km + (size_t)(bn * 128 + row) * DK + c4 * 4);
        uint32_t off = (row * SSP + c4 * 4) * 2;
        __half hx, hy, hz, hw;
        hx = __float2half_rn(vq.x); hy = __float2half_rn(vq.y);
        hz = __float2half_rn(vq.z); hw = __float2half_rn(vq.w);
        __half2 qh01 = __halves2half2(hx, hy), qh23 = __halves2half2(hz, hw);
        __half2 ql01 = __halves2half2(__float2half_rn(vq.x - __half2float(hx)),
                                      __float2half_rn(vq.y - __half2float(hy)));
        __half2 ql23 = __halves2half2(__float2half_rn(vq.z - __half2float(hz)),
                                      __float2half_rn(vq.w - __half2float(hw)));
        *(uint2*)(ssm + (uQh - sb) + off) = make_uint2(*(uint32_t*)&qh01, *(uint32_t*)&qh23);
        *(uint2*)(ssm + (uQl - sb) + off) = make_uint2(*(uint32_t*)&ql01, *(uint32_t*)&ql23);
        hx = __float2half_rn(vk.x); hy = __float2half_rn(vk.y);
        hz = __float2half_rn(vk.z); hw = __float2half_rn(vk.w);
        __half2 kh01 = __halves2half2(hx, hy), kh23 = __halves2half2(hz, hw);
        __half2 kl01 = __halves2half2(__float2half_rn(vk.x - __half2float(hx)),
                                      __float2half_rn(vk.y - __half2float(hy)));
        __half2 kl23 = __halves2half2(__float2half_rn(vk.z - __half2float(hz)),
                                      __float2half_rn(vk.w - __half2float(hw)));
        *(uint2*)(ssm + (uKh - sb) + off) = make_uint2(*(uint32_t*)&kh01, *(uint32_t*)&kh23);
        *(uint2*)(ssm + (uKl - sb) + off) = make_uint2(*(uint32_t*)&kl01, *(uint32_t*)&kl23);
    }
    __syncthreads();

    float acc[4][4][4];
#pragma unroll
    for (int i = 0; i < 4; i++)
#pragma unroll
        for (int j = 0; j < 4; j++)
#pragma unroll
            for (int q = 0; q < 4; q++) acc[i][j][q] = 0.0f;

    const int lrow = (lane & 7) + ((lane >> 3) & 1) * 8;
    const int lcol8 = (lane >> 4) * 8;

#pragma unroll
    for (int kk = 0; kk < 64; kk += 16) {
        const uint32_t boff = ((wn * 32 + lrow) * SSP + kk + lcol8) * 2;
        uint32_t bh[2][4], bl[2][4];
#pragma unroll
        for (int np = 0; np < 2; np++) {
            ldsm4(bh[np], uKh + boff + np * (16 * SSP * 2));
            ldsm4(bl[np], uKl + boff + np * (16 * SSP * 2));
        }
        const uint32_t aoff = ((wm * 64 + lrow) * SSP + kk + lcol8) * 2;
#pragma unroll
        for (int mt = 0; mt < 4; mt++) {
            uint32_t ah[4], al[4];
            ldsm4(ah, uQh + aoff + mt * (16 * SSP * 2));
            ldsm4(al, uQl + aoff + mt * (16 * SSP * 2));
#pragma unroll
            for (int nt = 0; nt < 4; nt++) {
                const int np = nt >> 1, sel = nt & 1;
                mma_f16(acc[mt][nt], ah, bh[np][sel], bh[np][sel + 2]);
                mma_f16(acc[mt][nt], ah, bl[np][sel], bl[np][sel + 2]);
                mma_f16(acc[mt][nt], al, bh[np][sel], bh[np][sel + 2]);
            }
        }
    }

    // Epilogue: s = acc/8 + gumbel;  Eh = fp16(exp(s - 13))
#pragma unroll
    for (int mt = 0; mt < 4; mt++) {
        uint32_t m0 = bm * 128 + wm * 64 + mt * 16 + (lane >> 2);
#pragma unroll
        for (int nt = 0; nt < 4; nt++) {
            uint32_t col = bn * 128 + wn * 32 + nt * 8 + 2 * (lane & 3);
            uint32_t e0 = m0 * (uint32_t)NL + col;
            uint32_t e1 = (m0 + 8) * (uint32_t)NL + col;
            float s00 = acc[mt][nt][0] * 0.125f + gumbel_at(e0)     - ESHIFT;
            float s01 = acc[mt][nt][1] * 0.125f + gumbel_at(e0 + 1) - ESHIFT;
            float s10 = acc[mt][nt][2] * 0.125f + gumbel_at(e1)     - ESHIFT;
            float s11 = acc[mt][nt][3] * 0.125f + gumbel_at(e1 + 1) - ESHIFT;
            __half2 p0 = __floats2half2_rn(__expf(s00), __expf(s01));
            __half2 p1 = __floats2half2_rn(__expf(s10), __expf(s11));
            *(uint32_t*)(g_Eh + e0) = *(uint32_t*)&p0;
            *(uint32_t*)(g_Eh + e1) = *(uint32_t*)&p1;
        }
    }
}

// ---------------------------------------------------------------------------
// Kernel B: row sums of Eh -> g_inv;  p_attn fp32 = Eh * inv (the only
// fp32 softmax write). One CTA of 256 threads per row.
// ---------------------------------------------------------------------------
__global__ __launch_bounds__(256)
void rowsum_kernel(float* __restrict__ P)
{
    __shared__ float red[8];
    const int r = blockIdx.x, t = threadIdx.x;
    const uint2* eh = (const uint2*)(g_Eh + (size_t)r * NL);   // 4 fp16 per uint2
    float4* g = (float4*)(P + (size_t)r * NL);

    uint2 v[4];
    float s = 0.0f;
    float2 f01[4], f23[4];
#pragma unroll
    for (int q = 0; q < 4; q++) {
        v[q] = eh[t + 256 * q];
        f01[q] = __half22float2(*(__half2*)&v[q].x);
        f23[q] = __half22float2(*(__half2*)&v[q].y);
        s += (f01[q].x + f01[q].y) + (f23[q].x + f23[q].y);
    }
#pragma unroll
    for (int o = 16; o > 0; o >>= 1)
        s += __shfl_xor_sync(0xffffffffu, s, o);
    if ((t & 31) == 0) red[t >> 5] = s;
    __syncthreads();
    float tot = red[0];
#pragma unroll
    for (int w = 1; w < 8; w++) tot += red[w];
    float inv = 1.0f / tot;
    if (t == 0) g_inv[r] = inv;

#pragma unroll
    for (int q = 0; q < 4; q++) {
        float4 o;
        o.x = f01[q].x * inv; o.y = f01[q].y * inv;
        o.z = f23[q].x * inv; o.w = f23[q].y * inv;
        g[t + 256 * q] = o;
    }
}

// ---------------------------------------------------------------------------
// Kernel B2: transpose V to fp16:  V[k][n] -> V^T fp16 [n][k]
// ---------------------------------------------------------------------------
__global__ __launch_bounds__(256)
void vsplit_kernel(const float* __restrict__ V)
{
    __shared__ float tile[32][33];
    const int n0 = blockIdx.x * 32, k0 = blockIdx.y * 32;
    const int tx = threadIdx.x & 31, ty = threadIdx.x >> 5;
#pragma unroll
    for (int i = 0; i < 32; i += 8)
        tile[ty + i][tx] = V[(size_t)(k0 + ty + i) * NC + n0 + tx];
    __syncthreads();
#pragma unroll
    for (int i = 0; i < 32; i += 8) {
        float f = tile[tx][ty + i];
        g_VhT[(size_t)(n0 + ty + i) * NL + k0 + tx] = __float2half_rn(f);
    }
}

// ---------------------------------------------------------------------------
// Kernel C: out = (Eh @ Vh) * inv[m].  R10 config: CTA 64x128, 128 thr,
// 4 warps, warp 64x32, BK=32, 3-stage cp.async ring, 4 CTAs/SM.
// ---------------------------------------------------------------------------
#define SP 40
#define P_ARR (64 * SP * 2)
#define V_ARR (128 * SP * 2)
#define STAGE_BYTES (P_ARR + V_ARR)
#define NSTAGE 3
#define PV_SMEM (NSTAGE * STAGE_BYTES)

__global__ __launch_bounds__(128, 4)
void pv_kernel(float* __restrict__ O)
{
    extern __shared__ __align__(16) char dsm[];
    const uint32_t sbase = smem_to_u32(dsm);

    const int tid = threadIdx.x;
    const int lane = tid & 31, wn = tid >> 5;
    const int bn = blockIdx.x, bm = blockIdx.y;

    const __half* srcP = g_Eh + (size_t)(bm * 64) * NL;
    const __half* srcV = g_VhT + (size_t)(bn * 128) * NL;

    float acc[4][4][4];
#pragma unroll
    for (int i = 0; i < 4; i++)
#pragma unroll
        for (int j = 0; j < 4; j++)
#pragma unroll
            for (int q = 0; q < 4; q++) acc[i][j][q] = 0.0f;

    const int lrow = (lane & 7) + ((lane >> 3) & 1) * 8;
    const int lcol8 = (lane >> 4) * 8;

    auto load_stage = [&](int st, int k0) {
        uint32_t stb = sbase + st * STAGE_BYTES;
#pragma unroll
        for (int u = 0; u < 2; u++) {
            int idx = tid + 128 * u;
            int row = idx >> 2, kc = idx & 3;
            cpa16(stb + (row * SP + kc * 8) * 2, srcP + (size_t)row * NL + k0 + kc * 8);
        }
#pragma unroll
        for (int u = 0; u < 4; u++) {
            int idx = tid + 128 * u;
            int row = idx >> 2, kc = idx & 3;
            cpa16(stb + P_ARR + (row * SP + kc * 8) * 2, srcV + (size_t)row * NL + k0 + kc * 8);
        }
    };

    load_stage(0, 0);  CP_COMMIT();
    load_stage(1, 32); CP_COMMIT();

    const int NCH = NL / 32;
    for (int c = 0; c < NCH; c++) {
        CP_WAIT1();
        __syncthreads();
        if (c + 2 < NCH) load_stage((c + 2) % NSTAGE, (c + 2) * 32);
        CP_COMMIT();

        const uint32_t stb = sbase + (c % NSTAGE) * STAGE_BYTES;
        const uint32_t uPh = stb, uVh = stb + P_ARR;

#pragma unroll
        for (int kk = 0; kk < 32; kk += 16) {
            const uint32_t aoff = (lrow * SP + kk + lcol8) * 2;
            const uint32_t boff = ((wn * 32 + lrow) * SP + kk + lcol8) * 2;
            uint32_t ah[4][4];
#pragma unroll
            for (int mt = 0; mt < 4; mt++)
                ldsm4(ah[mt], uPh + aoff + mt * (16 * SP * 2));
            uint32_t bh[2][4];
#pragma unroll
            for (int np = 0; np < 2; np++)
                ldsm4(bh[np], uVh + boff + np * (16 * SP * 2));
#pragma unroll
            for (int mt = 0; mt < 4; mt++)
#pragma unroll
                for (int nt = 0; nt < 4; nt++) {
                    const int np = nt >> 1, sel = nt & 1;
                    mma_f16(acc[mt][nt], ah[mt], bh[np][sel], bh[np][sel + 2]);
                }
        }
    }

    // Epilogue: multiply by per-row 1/sum
#pragma unroll
    for (int mt = 0; mt < 4; mt++) {
        int m = bm * 64 + mt * 16 + (lane >> 2);
        float inv0 = g_inv[m];
        float inv1 = g_inv[m + 8];
#pragma unroll
        for (int nt = 0; nt < 4; nt++) {
            int col = bn * 128 + wn * 32 + nt * 8 + 2 * (lane & 3);
            float2 v0 = make_float2(acc[mt][nt][0] * inv0, acc[mt][nt][1] * inv0);
            float2 v1 = make_float2(acc[mt][nt][2] * inv1, acc[mt][nt][3] * inv1);
            *(float2*)(O + (size_t)m * NC + col)       = v0;
            *(float2*)(O + (size_t)(m + 8) * NC + col) = v1;
        }
    }
}

// ---------------------------------------------------------------------------
// Launch (single stream — no stream/event objects, allocation-free)
// ---------------------------------------------------------------------------
extern "C" void kernel_launch(void* const* d_in, const int* in_sizes, int n_in,
                              void* d_out, int out_size) {
    const float* Q  = (const float*)d_in[0];   // [16384, 64]
    const float* Km = (const float*)d_in[1];   // [4096, 64]
    const float* V  = (const float*)d_in[2];   // [4096, 1024]
    float* out = (float*)d_out;                // [16384, 1024]
    float* P   = out + OUT_ELEMS;              // [16384, 4096] p_attn

    static bool attr_done = false;
    if (!attr_done) {
        cudaFuncSetAttribute(pv_kernel, cudaFuncAttributeMaxDynamicSharedMemorySize, PV_SMEM);
        cudaFuncSetAttribute(score_kernel, cudaFuncAttributeMaxDynamicSharedMemorySize, SC_SMEM);
        attr_done = true;
    }

    dim3 gA(NL / 128, NG / 128);               // 32 x 128
    score_kernel<<<gA, 256, SC_SMEM>>>(Q, Km);

    vsplit_kernel<<<dim3(NC / 32, NL / 32), 256>>>(V);

    rowsum_kernel<<<NG, 256>>>(P);

    dim3 gC(NC / 128, NG / 64);                // 8 x 256
    pv_kernel<<<gC, 128, PV_SMEM>>>(out);
}